// round 9
// baseline (speedup 1.0000x reference)
#include <cuda_runtime.h>
#include <cuda_bf16.h>
#include <math_constants.h>

// Problem constants
#define NPTS   8192
#define KCOMP  64
#define NBINS  256
#define NBLK   256           // one block per bin
#define NTHR   512           // 16 warps
#define NWARP  16
#define EPW    (NPTS / NWARP)   // 512 elements filtered per warp
#define RPW    (EPW / 32)       // 16 rounds per warp

// KDE: bw = 0.5*128/8192 = 2^-7 exactly -> exp(-8192*d^2) = exp2(CKDE*d^2)
#define LOG2E 1.4426950408889634
__device__ __constant__ float CKDE = (float)(-8192.0 * LOG2E);
__device__ __constant__ float NORM = (float)(1.0 / (2.5066282746310002 * 0.0078125 * 8192.0));
// ex2.ftz -> exact 0 for |d| > 0.10327. Fixed bins: width 0.052, window +/-2 bins
// covers +/-0.104 > R. Clamped edge bins only merge far points (contribute 0).
#define BIN_LO  (-6.656f)
#define BIN_IW  (19.230769230769230769f)   // 1/0.052

// Globals (no allocation allowed). Only cross-block state: result partials + ticket.
__device__ float g_bsum[NBLK];
__device__ int   g_ticket = 0;   // self-resets each call -> graph-replay safe

__device__ __forceinline__ float ex2(float x) {
    float r;
    asm("ex2.approx.ftz.f32 %0, %1;" : "=f"(r) : "f"(x));
    return r;
}

__device__ __forceinline__ int bin_of(float v) {
    int b = (int)floorf((v - BIN_LO) * BIN_IW);
    return max(min(b, NBINS - 1), 0);
}

__global__ __launch_bounds__(NTHR, 2)
void gmm_one(const float* __restrict__ x,  const float* __restrict__ wl,
             const float* __restrict__ mu, const float* __restrict__ lv,
             float* __restrict__ out) {
    // seg: per-warp filter segments; later reused as the j-list (segments dead then)
    __shared__ float seg[NPTS];          // 32 KB
    __shared__ float ws[NPTS];           // 32 KB compacted candidate window
    __shared__ float smn[KCOMP], scf[KCOMP], sa[KCOMP];
    __shared__ int   scnt[NWARP], soff[NWARP];
    __shared__ int   s_wtot, s_jcnt, s_last;
    __shared__ float wsum[NWARP];

    const int tid  = threadIdx.x;
    const int lane = tid & 31;
    const int w    = tid >> 5;
    const int c    = blockIdx.x;         // this block's bin

    // ---- mixture constants, redundant per block (race-free: direct LDG) ----
    if (tid < KCOMP) {
        float m = -CUDART_INF_F;
        #pragma unroll
        for (int i = 0; i < KCOMP; i++) m = fmaxf(m, __ldg(&wl[i]));
        float ss = 0.0f;
        #pragma unroll
        for (int i = 0; i < KCOMP; i++) ss += __expf(__ldg(&wl[i]) - m);
        float wgt = __expf(__ldg(&wl[tid]) - m) / ss;
        float var = __expf(lv[tid]);
        smn[tid] = mu[tid];
        scf[tid] = wgt * rsqrtf(6.283185307179586f * var);
        sa[tid]  = (float)(-0.5 * LOG2E) / var;
    }

    // ---- filter: keep points with bin in [c-2, c+2], order-preserving -------
    int cnt = 0;
    #pragma unroll 4
    for (int r = 0; r < RPW; r++) {
        float xv = x[(w * RPW + r) * 32 + lane];          // coalesced
        int b = bin_of(xv);
        bool keep = (unsigned)(b - c + 2) <= 4u;
        unsigned m = __ballot_sync(0xffffffffu, keep);
        if (keep) seg[w * EPW + cnt + __popc(m & ((1u << lane) - 1u))] = xv;
        cnt += __popc(m);
    }
    if (lane == 0) scnt[w] = cnt;
    __syncthreads();

    // ---- compact 16 segments -> contiguous ws -------------------------------
    if (tid < 32) {
        int v = (lane < NWARP) ? scnt[lane] : 0;
        int incl = v;
        #pragma unroll
        for (int o = 1; o < 32; o <<= 1) {
            int u = __shfl_up_sync(0xffffffffu, incl, o);
            if (lane >= o) incl += u;
        }
        if (lane < NWARP) soff[lane] = incl - v;
        if (lane == NWARP - 1) s_wtot = incl;
    }
    __syncthreads();
    {
        int dst = soff[w], n = scnt[w];
        for (int i = lane; i < n; i += 32) ws[dst + i] = seg[w * EPW + i];
    }
    __syncthreads();

    // ---- build j-list (bin == c) from ws; warp 0, deterministic order -------
    // seg buffer is dead now -> reuse as jl
    float* jl = seg;
    const int wtot = s_wtot;
    if (w == 0) {
        int jc = 0;
        for (int i0 = 0; i0 < wtot; i0 += 32) {
            float v = 0.0f; bool k = false;
            if (i0 + lane < wtot) { v = ws[i0 + lane]; k = (bin_of(v) == c); }
            unsigned m = __ballot_sync(0xffffffffu, k);
            if (k) jl[jc + __popc(m & ((1u << lane) - 1u))] = v;
            jc += __popc(m);
        }
        if (lane == 0) {
            if (jc & 1) { jl[jc] = 1e30f; jc++; }   // sentinel: contributes exact 0
            s_jcnt = jc;
        }
    }
    __syncthreads();

    // ---- main: pairs of j's round-robin over warps --------------------------
    const int   jcnt = s_jcnt;
    const float ck   = CKDE;
    float wacc = 0.0f;
    for (int t = w; t < (jcnt >> 1); t += NWARP) {
        float xa = jl[2 * t], xb = jl[2 * t + 1];
        float A = 0.0f, B = 0.0f;
        #pragma unroll 2
        for (int i = lane; i < wtot; i += 32) {
            float v = ws[i];
            float d1 = xa - v; A += ex2(ck * d1 * d1);   // exact sub for close pairs
            float d2 = xb - v; B += ex2(ck * d2 * d2);
        }
        float d, ma, mb;
        d = xa - smn[lane];      ma  = scf[lane]      * ex2(sa[lane]      * d * d);
        d = xa - smn[lane + 32]; ma += scf[lane + 32] * ex2(sa[lane + 32] * d * d);
        d = xb - smn[lane];      mb  = scf[lane]      * ex2(sa[lane]      * d * d);
        d = xb - smn[lane + 32]; mb += scf[lane + 32] * ex2(sa[lane + 32] * d * d);
        float ta = ma - NORM * A;
        float tb = mb - NORM * B;
        #pragma unroll
        for (int o = 16; o > 0; o >>= 1) {
            ta += __shfl_xor_sync(0xffffffffu, ta, o);
            tb += __shfl_xor_sync(0xffffffffu, tb, o);
        }
        wacc += ta * ta + tb * tb;     // xor-butterfly: same value in all lanes
    }
    if (lane == 0) wsum[w] = wacc;
    __syncthreads();

    if (tid == 0) {
        float v = 0.0f;
        #pragma unroll
        for (int p = 0; p < NWARP; p++) v += wsum[p];
        g_bsum[c] = v;
        __threadfence();
        int tk = atomicAdd(&g_ticket, 1);
        s_last = (tk == NBLK - 1);
    }
    __syncthreads();

    // ---- last block: deterministic final reduction --------------------------
    if (s_last) {
        __threadfence();                  // acquire: order reads after ticket
        float v = (tid < NBLK) ? g_bsum[tid] : 0.0f;
        ws[tid] = v;                      // reuse ws as reduction scratch
        __syncthreads();
        #pragma unroll
        for (int off = 256; off > 0; off >>= 1) {
            if (tid < off) ws[tid] += ws[tid + off];
            __syncthreads();
        }
        if (tid == 0) {
            out[0] = ws[0];
            g_ticket = 0;                 // reset for next graph replay
        }
    }
}

extern "C" void kernel_launch(void* const* d_in, const int* in_sizes, int n_in,
                              void* d_out, int out_size) {
    const float* x  = (const float*)d_in[0];  // [8192]
    const float* wl = (const float*)d_in[1];  // [64] weight_logits
    const float* mu = (const float*)d_in[2];  // [64] means
    const float* lv = (const float*)d_in[3];  // [64] log_vars
    float* out = (float*)d_out;

    gmm_one<<<NBLK, NTHR>>>(x, wl, mu, lv, out);
}

// round 10
// speedup vs baseline: 1.4528x; 1.4528x over previous
#include <cuda_runtime.h>
#include <cuda_bf16.h>
#include <math_constants.h>

// Problem constants
#define NPTS    8192
#define KCOMP   64
#define NBINS   256
#define MBLK    1024         // main blocks
#define WPB     8            // warps (j's) per main block
#define HSTRIDE 257          // padded stride for warp-private hists (bank-conflict-free)

// KDE: bw = 0.5*128/8192 = 2^-7 exactly  ->  exp(-8192*d^2) = exp2(CKDE*d^2)
#define LOG2E 1.4426950408889634
__device__ __constant__ float CKDE = (float)(-8192.0 * LOG2E);
__device__ __constant__ float NORM = (float)(1.0 / (2.5066282746310002 * 0.0078125 * 8192.0));
// ex2.ftz -> exact 0 for |d| > 0.10327. Fixed bins: width 0.052, +/-2-bin window
// covers +/-0.104 > R. Edge clamping only EXTENDS windows -> correct for any input.
#define BIN_LO  (-6.656f)
#define BIN_IW  (19.230769230769230769f)   // 1/0.052

// Scratch (device globals — no allocation allowed)
__device__ __align__(16) float g_xs[NPTS];   // x counting-sorted by bin
__device__ int   g_binstart[NBINS + 1];      // exclusive-scan offsets; [NBINS] = NPTS
__device__ float g_coef[KCOMP];              // w_k / sqrt(2*pi*var_k)
__device__ float g_a[KCOMP];                 // -0.5*log2e / var_k
__device__ float g_bsum[MBLK];
__device__ int   g_ticket = 0;               // self-resets each call

__device__ __forceinline__ float ex2(float x) {
    float r;
    asm("ex2.approx.ftz.f32 %0, %1;" : "=f"(r) : "f"(x));
    return r;
}

__device__ __forceinline__ int bin_of(float v) {
    int b = (int)floorf((v - BIN_LO) * BIN_IW);
    return max(min(b, NBINS - 1), 0);
}

// ---------------------------------------------------------------------------
// 1) Prep: counting sort with warp-private histograms; the atomicAdd RETURN
//    VALUE is the element's rank within (warp, bin) -> no cursor atomics, no
//    cross-warp contention. Plus softmax constants. 1 block x 1024 threads.
// ---------------------------------------------------------------------------
__global__ __launch_bounds__(1024) void gmm_prep(const float* __restrict__ x,
                                                 const float* __restrict__ wl,
                                                 const float* __restrict__ lv) {
    __shared__ int h[HSTRIDE * 32];     // h[bin + HSTRIDE*warp]
    __shared__ int tot[NBINS];
    __shared__ int bs[NBINS + 1];

    const int t = threadIdx.x, lane = t & 31, w = t >> 5;

    // zero warp-private histograms
    #pragma unroll
    for (int i = t; i < HSTRIDE * 32; i += 1024) h[i] = 0;
    __syncthreads();

    // load 8 elements/thread; build hists; atomicAdd return = intra-(warp,bin) rank
    float xv[8];
    int   bidx[8], rank[8];
    #pragma unroll
    for (int e = 0; e < 8; e++) {
        float v = x[t + e * 1024];
        xv[e]   = v;
        int b   = bin_of(v);
        bidx[e] = b;
        rank[e] = atomicAdd(&h[b + HSTRIDE * w], 1);
    }
    __syncthreads();

    // per-bin exclusive scan across the 32 warps (in place); thread-per-bin.
    // Addresses b + HSTRIDE*k -> bank (b+k)%32: conflict-free across threads.
    if (t < NBINS) {
        int run = 0;
        #pragma unroll
        for (int k = 0; k < 32; k++) {
            int idx = t + HSTRIDE * k;
            int v = h[idx];
            h[idx] = run;
            run += v;
        }
        tot[t] = run;
    }
    __syncthreads();

    // warp 0: exclusive scan of 256 bin totals (8/lane serial + shfl scan)
    if (t < 32) {
        int v[8], p[8], run = 0;
        #pragma unroll
        for (int k = 0; k < 8; k++) {
            v[k] = tot[t * 8 + k];
            p[k] = run;
            run += v[k];
        }
        int incl = run;
        #pragma unroll
        for (int o = 1; o < 32; o <<= 1) {
            int u = __shfl_up_sync(0xffffffffu, incl, o);
            if (lane >= o) incl += u;
        }
        int excl = incl - run;
        #pragma unroll
        for (int k = 0; k < 8; k++) bs[t * 8 + k] = excl + p[k];
        if (t == 31) bs[NBINS] = incl;   // == NPTS
    }
    __syncthreads();

    // scatter: pos = binstart + warp-prefix + rank (unique by construction)
    #pragma unroll
    for (int e = 0; e < 8; e++) {
        int pos = bs[bidx[e]] + h[bidx[e] + HSTRIDE * w] + rank[e];
        g_xs[pos] = xv[e];
    }
    if (t <= NBINS) g_binstart[t] = bs[t];

    // softmax + per-component constants (direct global reads -> race-free)
    if (t < KCOMP) {
        float m = -CUDART_INF_F;
        #pragma unroll
        for (int i = 0; i < KCOMP; i++) m = fmaxf(m, __ldg(&wl[i]));
        float ssum = 0.0f;
        #pragma unroll
        for (int i = 0; i < KCOMP; i++) ssum += __expf(__ldg(&wl[i]) - m);
        float wgt = __expf(__ldg(&wl[t]) - m) / ssum;
        float var = __expf(lv[t]);
        g_coef[t] = wgt * rsqrtf(6.283185307179586f * var);
        g_a[t]    = (float)(-0.5 * LOG2E) / var;
    }
}

// ---------------------------------------------------------------------------
// 2) Main (R6 structure, best measured): one warp per sorted j; lanes stride
//    the +/-2-bin candidate window with coalesced L1-resident LDG.
//    1024 blocks x 256 threads -> fine-grained HW load balancing.
// ---------------------------------------------------------------------------
__global__ __launch_bounds__(256) void gmm_main(const float* __restrict__ means,
                                                float* __restrict__ out) {
    __shared__ float smn[KCOMP], scf[KCOMP], sa[KCOMP];
    __shared__ float wsum[WPB];
    __shared__ float rs[256];
    __shared__ int   s_last;

    int tid = threadIdx.x, lane = tid & 31, w = tid >> 5;
    if (tid < KCOMP) {
        smn[tid] = means[tid];
        scf[tid] = g_coef[tid];
        sa[tid]  = g_a[tid];
    }
    __syncthreads();

    int j = blockIdx.x * WPB + w;
    float xj = g_xs[j];                        // broadcast
    int b = bin_of(xj);                        // identical formula to prep
    int c0 = __ldg(&g_binstart[max(b - 2, 0)]);
    int c1 = __ldg(&g_binstart[min(b + 3, NBINS)]);

    float ck = CKDE;
    float acc = 0.0f;
    #pragma unroll 4
    for (int i = c0 + lane; i < c1; i += 32) {
        float d = xj - g_xs[i];                // Sterbenz-exact for close pairs
        acc += ex2(ck * d * d);
    }

    // mixture pdf: 2 components per lane
    float d1 = xj - smn[lane];
    float mixp = scf[lane] * ex2(sa[lane] * d1 * d1);
    float d2 = xj - smn[lane + 32];
    mixp += scf[lane + 32] * ex2(sa[lane + 32] * d2 * d2);

    #pragma unroll
    for (int o = 16; o > 0; o >>= 1) {
        acc  += __shfl_xor_sync(0xffffffffu, acc, o);
        mixp += __shfl_xor_sync(0xffffffffu, mixp, o);
    }
    if (lane == 0) {
        float diff = mixp - acc * NORM;
        wsum[w] = diff * diff;
    }
    __syncthreads();

    if (tid == 0) {
        float v = 0.0f;
        #pragma unroll
        for (int p = 0; p < WPB; p++) v += wsum[p];
        g_bsum[blockIdx.x] = v;
        __threadfence();
        int tk = atomicAdd(&g_ticket, 1);
        s_last = (tk == MBLK - 1);
    }
    __syncthreads();

    if (s_last) {
        __threadfence();                       // acquire: order reads after ticket
        float v = 0.0f;
        #pragma unroll
        for (int q = 0; q < MBLK / 256; q++) v += g_bsum[tid + q * 256];
        rs[tid] = v;
        __syncthreads();
        #pragma unroll
        for (int off = 128; off > 0; off >>= 1) {
            if (tid < off) rs[tid] += rs[tid + off];
            __syncthreads();
        }
        if (tid == 0) {
            out[0] = rs[0];
            g_ticket = 0;   // reset for next graph replay
        }
    }
}

extern "C" void kernel_launch(void* const* d_in, const int* in_sizes, int n_in,
                              void* d_out, int out_size) {
    const float* x  = (const float*)d_in[0];  // [8192]
    const float* wl = (const float*)d_in[1];  // [64] weight_logits
    const float* mu = (const float*)d_in[2];  // [64] means
    const float* lv = (const float*)d_in[3];  // [64] log_vars
    float* out = (float*)d_out;

    gmm_prep<<<1, 1024>>>(x, wl, lv);
    gmm_main<<<MBLK, 256>>>(mu, out);
}